// round 1
// baseline (speedup 1.0000x reference)
#include <cuda_runtime.h>
#include <math.h>

#define BATCH 16
#define SEQ   1024
#define DM    512
#define NH    8
#define HD    64
#define NB    (NH*BATCH)        // 128 head-major batches
#define NEGV  (-4294967295.0f)  // float(-2**32+1)

// Scratch (device globals: allocation-free per harness rules). 4 x 32 MB.
__device__ float g_Q[(size_t)NB*SEQ*HD];
__device__ float g_K[(size_t)NB*SEQ*HD];
__device__ float g_V[(size_t)NB*SEQ*HD];
__device__ float g_A[(size_t)NB*SEQ*HD];

// ---------------------------------------------------------------------------
// QKV projection: P = x @ W + b, scattered to head-major [h*B+b][s][hd]
// 64x64 tile per block, BK=16, 256 threads, 4x4 per thread.
// ---------------------------------------------------------------------------
__global__ __launch_bounds__(256) void proj_qkv_kernel(
    const float* __restrict__ x,
    const float* __restrict__ wq, const float* __restrict__ bq,
    const float* __restrict__ wk, const float* __restrict__ bk,
    const float* __restrict__ wv, const float* __restrict__ bv)
{
    __shared__ float As[16*68];   // [k][m] transposed
    __shared__ float Bs[16*68];   // [k][n]

    const float* w; const float* bias; float* dst;
    if (blockIdx.z == 0)      { w = wq; bias = bq; dst = g_Q; }
    else if (blockIdx.z == 1) { w = wk; bias = bk; dst = g_K; }
    else                      { w = wv; bias = bv; dst = g_V; }

    const int m0 = blockIdx.x * 64;
    const int n0 = blockIdx.y * 64;
    const int tid = threadIdx.x;
    const int ty = tid >> 4, tx = tid & 15;
    const int am = tid >> 2,  ak = (tid & 3) * 4;   // A loader: row am, k-offset ak
    const int bk_ = tid >> 4, bn = (tid & 15) * 4;  // B loader: k-row, n-offset

    float acc[4][4];
    #pragma unroll
    for (int i = 0; i < 4; i++)
        #pragma unroll
        for (int j = 0; j < 4; j++) acc[i][j] = 0.f;

    for (int k0 = 0; k0 < DM; k0 += 16) {
        float4 a4 = *(const float4*)(x + (size_t)(m0+am)*DM + k0 + ak);
        float4 b4 = *(const float4*)(w + (size_t)(k0+bk_)*DM + n0 + bn);
        __syncthreads();
        As[(ak+0)*68+am]=a4.x; As[(ak+1)*68+am]=a4.y;
        As[(ak+2)*68+am]=a4.z; As[(ak+3)*68+am]=a4.w;
        *(float4*)(Bs + bk_*68 + bn) = b4;
        __syncthreads();
        #pragma unroll
        for (int k = 0; k < 16; k++) {
            float4 av = *(const float4*)(As + k*68 + ty*4);
            float4 bv4 = *(const float4*)(Bs + k*68 + tx*4);
            float a[4] = {av.x, av.y, av.z, av.w};
            float b[4] = {bv4.x, bv4.y, bv4.z, bv4.w};
            #pragma unroll
            for (int i = 0; i < 4; i++)
                #pragma unroll
                for (int j = 0; j < 4; j++) acc[i][j] += a[i]*b[j];
        }
    }

    const int col0 = n0 + tx*4;           // all 4 cols in one head (n0 % 64 == 0)
    const int h  = col0 >> 6;
    const int q0 = col0 & 63;
    float4 bb4 = *(const float4*)(bias + col0);
    #pragma unroll
    for (int i = 0; i < 4; i++) {
        int row = m0 + ty*4 + i;
        int b = row >> 10, sI = row & 1023;
        float4 o = make_float4(acc[i][0]+bb4.x, acc[i][1]+bb4.y,
                               acc[i][2]+bb4.z, acc[i][3]+bb4.w);
        *(float4*)(dst + (((size_t)(h*BATCH + b))*SEQ + sI)*HD + q0) = o;
    }
}

// ---------------------------------------------------------------------------
// Fused attention: per (n, 64-row query tile):
//   S = Q K^T * 0.125 -> write raw_score -> mask -> online softmax -> acc += P V
// Block 256 threads (16x16), 4x4 micro-tile. Dynamic smem: Q / K|P / V tiles.
// ---------------------------------------------------------------------------
#define ATTN_SMEM (3*64*68*4)

__global__ __launch_bounds__(256) void attn_kernel(const int* __restrict__ pmask,
                                                   float* __restrict__ raw)
{
    extern __shared__ float smem[];
    float* Qs = smem;             // [64 d][68] transposed
    float* KP = smem + 64*68;     // K: [64 d][68] transposed, then reused as P: [64 r][68]
    float* Vs = smem + 2*64*68;   // [64 t][68] row-major

    const int n   = blockIdx.y;           // head-major batch 0..127
    const int qt  = blockIdx.x;           // query tile 0..15
    const int tid = threadIdx.x;
    const int ty = tid >> 4, tx = tid & 15;
    const int mb = n >> 3;                 // faithful mask-index mismatch: n // H
    const float scale = 0.125f;

    // Load Q tile transposed
    const float* qsrc = g_Q + ((size_t)n*SEQ + qt*64) * HD;
    #pragma unroll
    for (int it = 0; it < 4; it++) {
        int idx = tid + it*256;
        int r = idx >> 4;
        int d0 = (idx & 15) * 4;
        float4 v = *(const float4*)(qsrc + r*HD + d0);
        Qs[(d0+0)*68 + r] = v.x; Qs[(d0+1)*68 + r] = v.y;
        Qs[(d0+2)*68 + r] = v.z; Qs[(d0+3)*68 + r] = v.w;
    }

    float m_[4], l_[4], acc[4][4];
    #pragma unroll
    for (int i = 0; i < 4; i++) {
        m_[i] = -INFINITY; l_[i] = 0.f;
        #pragma unroll
        for (int j = 0; j < 4; j++) acc[i][j] = 0.f;
    }

    const float* ksrc = g_K + (size_t)n*SEQ*HD;
    const float* vsrc = g_V + (size_t)n*SEQ*HD;

    for (int kt = 0; kt < 16; kt++) {
        __syncthreads();   // previous PV reads of KP/Vs complete
        // Load K tile (transposed) and V tile (row-major)
        #pragma unroll
        for (int it = 0; it < 4; it++) {
            int idx = tid + it*256;
            int t = idx >> 4;
            int d0 = (idx & 15) * 4;
            float4 kv = *(const float4*)(ksrc + (size_t)(kt*64 + t)*HD + d0);
            KP[(d0+0)*68 + t] = kv.x; KP[(d0+1)*68 + t] = kv.y;
            KP[(d0+2)*68 + t] = kv.z; KP[(d0+3)*68 + t] = kv.w;
            float4 vv = *(const float4*)(vsrc + (size_t)(kt*64 + t)*HD + d0);
            *(float4*)(Vs + t*68 + d0) = vv;
        }
        __syncthreads();

        // S tile (unscaled dot products)
        float s[4][4];
        #pragma unroll
        for (int i = 0; i < 4; i++)
            #pragma unroll
            for (int j = 0; j < 4; j++) s[i][j] = 0.f;
        #pragma unroll 8
        for (int d = 0; d < 64; d++) {
            float4 a4 = *(const float4*)(Qs + d*68 + ty*4);
            float4 b4 = *(const float4*)(KP + d*68 + tx*4);
            float a[4] = {a4.x, a4.y, a4.z, a4.w};
            float b[4] = {b4.x, b4.y, b4.z, b4.w};
            #pragma unroll
            for (int i = 0; i < 4; i++)
                #pragma unroll
                for (int j = 0; j < 4; j++) s[i][j] += a[i]*b[j];
        }

        // Scale, write raw score (pre-mask), mask, local row max
        int4 mk = *(const int4*)(pmask + (size_t)mb*SEQ + kt*64 + tx*4);
        float lm[4], ls[4];
        #pragma unroll
        for (int i = 0; i < 4; i++) {
            float4 rw = make_float4(s[i][0]*scale, s[i][1]*scale,
                                    s[i][2]*scale, s[i][3]*scale);
            size_t ro = ((size_t)n*SEQ + qt*64 + ty*4 + i) * SEQ + kt*64 + tx*4;
            *(float4*)(raw + ro) = rw;
            s[i][0] = (mk.x != 0) ? rw.x : NEGV;
            s[i][1] = (mk.y != 0) ? rw.y : NEGV;
            s[i][2] = (mk.z != 0) ? rw.z : NEGV;
            s[i][3] = (mk.w != 0) ? rw.w : NEGV;
            lm[i] = fmaxf(fmaxf(s[i][0], s[i][1]), fmaxf(s[i][2], s[i][3]));
        }
        // Row max across the 16 lanes that share a row group
        #pragma unroll
        for (int i = 0; i < 4; i++)
            #pragma unroll
            for (int o = 8; o > 0; o >>= 1)
                lm[i] = fmaxf(lm[i], __shfl_xor_sync(0xffffffffu, lm[i], o));

        // Online softmax update
        #pragma unroll
        for (int i = 0; i < 4; i++) {
            float mn = fmaxf(m_[i], lm[i]);
            float corr = __expf(m_[i] - mn);
            float sum = 0.f;
            #pragma unroll
            for (int j = 0; j < 4; j++) {
                float p = __expf(s[i][j] - mn);
                s[i][j] = p;
                sum += p;
            }
            ls[i] = sum;
            m_[i] = mn;
            l_[i] *= corr;
            #pragma unroll
            for (int j = 0; j < 4; j++) acc[i][j] *= corr;
        }
        #pragma unroll
        for (int i = 0; i < 4; i++) {
            #pragma unroll
            for (int o = 8; o > 0; o >>= 1)
                ls[i] += __shfl_xor_sync(0xffffffffu, ls[i], o);
            l_[i] += ls[i];
        }

        __syncthreads();   // all K reads done; safe to overwrite KP with P
        #pragma unroll
        for (int i = 0; i < 4; i++)
            *(float4*)(KP + (ty*4+i)*68 + tx*4) =
                make_float4(s[i][0], s[i][1], s[i][2], s[i][3]);
        __syncthreads();

        // acc += P @ V
        #pragma unroll 4
        for (int t0 = 0; t0 < 64; t0 += 4) {
            float pr[4][4];
            #pragma unroll
            for (int i = 0; i < 4; i++) {
                float4 p4 = *(const float4*)(KP + (ty*4+i)*68 + t0);
                pr[i][0] = p4.x; pr[i][1] = p4.y; pr[i][2] = p4.z; pr[i][3] = p4.w;
            }
            #pragma unroll
            for (int tt = 0; tt < 4; tt++) {
                float4 v4 = *(const float4*)(Vs + (t0+tt)*68 + tx*4);
                #pragma unroll
                for (int i = 0; i < 4; i++) {
                    float p = pr[i][tt];
                    acc[i][0] += p*v4.x; acc[i][1] += p*v4.y;
                    acc[i][2] += p*v4.z; acc[i][3] += p*v4.w;
                }
            }
        }
    }

    // Normalize and store attn output (head-major)
    float* adst = g_A + ((size_t)n*SEQ + qt*64) * HD;
    #pragma unroll
    for (int i = 0; i < 4; i++) {
        float il = 1.f / l_[i];
        float4 o = make_float4(acc[i][0]*il, acc[i][1]*il,
                               acc[i][2]*il, acc[i][3]*il);
        *(float4*)(adst + (ty*4+i)*HD + tx*4) = o;
    }
}

// ---------------------------------------------------------------------------
// Output projection: out = heads @ wo + bo, gathering heads from g_A.
// ---------------------------------------------------------------------------
__global__ __launch_bounds__(256) void proj_out_kernel(
    const float* __restrict__ wo, const float* __restrict__ bo,
    float* __restrict__ out)
{
    __shared__ float As[16*68];
    __shared__ float Bs[16*68];

    const int m0 = blockIdx.x * 64;
    const int n0 = blockIdx.y * 64;
    const int tid = threadIdx.x;
    const int ty = tid >> 4, tx = tid & 15;
    const int am = tid >> 2,  ak = (tid & 3) * 4;
    const int bk_ = tid >> 4, bn = (tid & 15) * 4;

    const int rowA = m0 + am;
    const int bA = rowA >> 10, sA = rowA & 1023;

    float acc[4][4];
    #pragma unroll
    for (int i = 0; i < 4; i++)
        #pragma unroll
        for (int j = 0; j < 4; j++) acc[i][j] = 0.f;

    for (int k0 = 0; k0 < DM; k0 += 16) {
        int kk = k0 + ak;                   // 4 consecutive, within one head
        int h = kk >> 6, v0 = kk & 63;
        float4 a4 = *(const float4*)(g_A + (((size_t)(h*BATCH + bA))*SEQ + sA)*HD + v0);
        float4 b4 = *(const float4*)(wo + (size_t)(k0+bk_)*DM + n0 + bn);
        __syncthreads();
        As[(ak+0)*68+am]=a4.x; As[(ak+1)*68+am]=a4.y;
        As[(ak+2)*68+am]=a4.z; As[(ak+3)*68+am]=a4.w;
        *(float4*)(Bs + bk_*68 + bn) = b4;
        __syncthreads();
        #pragma unroll
        for (int k = 0; k < 16; k++) {
            float4 av = *(const float4*)(As + k*68 + ty*4);
            float4 bv4 = *(const float4*)(Bs + k*68 + tx*4);
            float a[4] = {av.x, av.y, av.z, av.w};
            float b[4] = {bv4.x, bv4.y, bv4.z, bv4.w};
            #pragma unroll
            for (int i = 0; i < 4; i++)
                #pragma unroll
                for (int j = 0; j < 4; j++) acc[i][j] += a[i]*b[j];
        }
    }

    const int col0 = n0 + tx*4;
    float4 bb4 = *(const float4*)(bo + col0);
    #pragma unroll
    for (int i = 0; i < 4; i++) {
        int row = m0 + ty*4 + i;
        float4 o = make_float4(acc[i][0]+bb4.x, acc[i][1]+bb4.y,
                               acc[i][2]+bb4.z, acc[i][3]+bb4.w);
        *(float4*)(out + (size_t)row*DM + col0) = o;
    }
}

// ---------------------------------------------------------------------------
extern "C" void kernel_launch(void* const* d_in, const int* in_sizes, int n_in,
                              void* d_out, int out_size)
{
    (void)in_sizes; (void)n_in; (void)out_size;
    const float* x  = (const float*)d_in[0];
    const int*   pm = (const int*)  d_in[1];
    const float* wq = (const float*)d_in[2];
    const float* bq = (const float*)d_in[3];
    const float* wk = (const float*)d_in[4];
    const float* bk = (const float*)d_in[5];
    const float* wv = (const float*)d_in[6];
    const float* bv = (const float*)d_in[7];
    const float* wo = (const float*)d_in[8];
    const float* bo = (const float*)d_in[9];

    float* out = (float*)d_out;
    float* raw = out + (size_t)BATCH*SEQ*DM;   // tuple order: (out, raw_score)

    // Opt-in to >48KB dynamic smem (idempotent; first call is outside capture).
    cudaFuncSetAttribute(attn_kernel, cudaFuncAttributeMaxDynamicSharedMemorySize,
                         ATTN_SMEM);

    proj_qkv_kernel<<<dim3((BATCH*SEQ)/64, DM/64, 3), 256>>>(x, wq, bq, wk, bk, wv, bv);
    attn_kernel<<<dim3(SEQ/64, NB), 256, ATTN_SMEM>>>(pm, raw);
    proj_out_kernel<<<dim3((BATCH*SEQ)/64, DM/64), 256>>>(wo, bo, out);
}